// round 6
// baseline (speedup 1.0000x reference)
#include <cuda_runtime.h>
#include <cuda_bf16.h>
#include <math_constants.h>
#include <cstdint>

#define NROWS 16384
#define KCODES 8192
#define DIM 256
#define CAP 64
#define NTILES 64          // 8192 / 128 codes per tile
#define PADB 528           // smem row pitch bytes (256 bf16 = 512 + 16 pad)
#define ZSZ (128 * PADB)   // 67584 per tile buffer
#define SMEM_TOT (3 * ZSZ + 512)

// ---------------- static device scratch ----------------
__device__ __align__(16) __nv_bfloat16 g_zb[NROWS * DIM];
__device__ __align__(16) __nv_bfloat16 g_eb[KCODES * DIM];
__device__ int    g_cand[NROWS * CAP];
__device__ int    g_cnt[NROWS];
__device__ unsigned char g_over[NROWS];
__device__ float  g_x2[NROWS];
__device__ float  g_e2[KCODES];
__device__ int    g_e2max_bits;
__device__ int    g_codes[NROWS];
__device__ double g_part[NROWS];

// ---------------- base-target PTX helpers ----------------
__device__ __forceinline__ uint32_t smem_u32(const void* p) {
    uint32_t a;
    asm("{ .reg .u64 t; cvta.to.shared.u64 t, %1; cvt.u32.u64 %0, t; }" : "=r"(a) : "l"(p));
    return a;
}
#define CPA16(dst, src) \
    asm volatile("cp.async.cg.shared.global [%0], [%1], 16;" :: "r"(dst), "l"(src))
#define CPA_COMMIT() asm volatile("cp.async.commit_group;" ::: "memory")
#define CPA_WAIT1()  asm volatile("cp.async.wait_group 1;" ::: "memory")
#define CPA_WAIT0()  asm volatile("cp.async.wait_group 0;" ::: "memory")
#define LDSM4(r, addr) \
    asm volatile("ldmatrix.sync.aligned.m8n8.x4.shared.b16 {%0,%1,%2,%3}, [%4];" \
                 : "=r"((r)[0]), "=r"((r)[1]), "=r"((r)[2]), "=r"((r)[3]) : "r"(addr))

__device__ __forceinline__ void mma16816(float* c, const uint32_t* a, uint32_t b0, uint32_t b1) {
    asm volatile(
        "mma.sync.aligned.m16n8k16.row.col.f32.bf16.bf16.f32 "
        "{%0,%1,%2,%3},{%4,%5,%6,%7},{%8,%9},{%0,%1,%2,%3};"
        : "+f"(c[0]), "+f"(c[1]), "+f"(c[2]), "+f"(c[3])
        : "r"(a[0]), "r"(a[1]), "r"(a[2]), "r"(a[3]), "r"(b0), "r"(b1));
}

// ---------------- aux kernels ----------------
__global__ void conv_kernel(const float* __restrict__ z, const float* __restrict__ e) {
    if (blockIdx.x == 0 && threadIdx.x == 0) g_e2max_bits = 0;
    size_t v4 = (size_t)blockIdx.x * 256 + threadIdx.x;
    const size_t NZ4 = (size_t)NROWS * DIM / 4;
    if (v4 < NZ4) {
        float4 f = ((const float4*)z)[v4];
        __nv_bfloat162* d = (__nv_bfloat162*)g_zb + v4 * 2;
        d[0] = __floats2bfloat162_rn(f.x, f.y);
        d[1] = __floats2bfloat162_rn(f.z, f.w);
    } else {
        size_t u = v4 - NZ4;
        float4 f = ((const float4*)e)[u];
        __nv_bfloat162* d = (__nv_bfloat162*)g_eb + u * 2;
        d[0] = __floats2bfloat162_rn(f.x, f.y);
        d[1] = __floats2bfloat162_rn(f.z, f.w);
    }
}

__global__ void e2_kernel(const float* __restrict__ emb) {
    int k = blockIdx.x * 8 + (threadIdx.x >> 5);
    int lane = threadIdx.x & 31;
    const float* p = emb + (size_t)k * DIM;
    float s = 0.f;
#pragma unroll
    for (int i = 0; i < 8; i++) { float v = p[lane + 32 * i]; s = __fmaf_rn(v, v, s); }
#pragma unroll
    for (int o = 16; o; o >>= 1) s += __shfl_down_sync(0xffffffffu, s, o);
    if (lane == 0) { g_e2[k] = s; atomicMax(&g_e2max_bits, __float_as_int(s)); }
}

__global__ void x2_kernel(const float* __restrict__ z) {
    int row = blockIdx.x * 8 + (threadIdx.x >> 5);
    int lane = threadIdx.x & 31;
    const float* p = z + (size_t)row * DIM;
    float s = 0.f;
#pragma unroll
    for (int i = 0; i < 8; i++) { float v = p[lane + 32 * i]; s = __fmaf_rn(v, v, s); }
#pragma unroll
    for (int o = 16; o; o >>= 1) s += __shfl_down_sync(0xffffffffu, s, o);
    if (lane == 0) g_x2[row] = s;
}

// ---------------- phase 1: mma.sync bf16 GEMM + dot-margin pruning ----------
__global__ __launch_bounds__(256, 1) void vq_mma() {
    extern __shared__ char sm[];
    int* scnt = (int*)(sm + 3 * ZSZ);
    const uint32_t sb = smem_u32(sm);
    const int tid = threadIdx.x, lane = tid & 31, w = tid >> 5;
    const int n0 = blockIdx.x * 128;

    if (tid < 128) scnt[tid] = 0;

    // prologue loads: z tile + emb tile 0 (one cp.async group)
    {
        const char* gz = (const char*)(g_zb + (size_t)n0 * DIM);
        const char* ge = (const char*)g_eb;
#pragma unroll
        for (int t = 0; t < 16; t++) {
            int i = tid + t * 256;
            int row = i >> 5, q = i & 31;
            CPA16(sb + row * PADB + q * 16, gz + row * 512 + q * 16);
        }
#pragma unroll
        for (int t = 0; t < 16; t++) {
            int i = tid + t * 256;
            int row = i >> 5, q = i & 31;
            CPA16(sb + ZSZ + row * PADB + q * 16, ge + row * 512 + q * 16);
        }
        CPA_COMMIT();
    }
    CPA_WAIT0();
    __syncthreads();

    // persistent A fragments: this warp's 16 rows x full D=256
    const int lm = lane >> 3, lr = lane & 7;
    uint32_t a[16][4];
    {
        uint32_t aAddr = sb + (uint32_t)(w * 16 + lr + (lm & 1) * 8) * PADB + ((lm >> 1) << 4);
#pragma unroll
        for (int ks = 0; ks < 16; ks++) LDSM4(a[ks], aAddr + ks * 32);
    }

    // pruning state: rows (w*16 + g) and (+8), g = lane>>2
    const int g = lane >> 2, tq = lane & 3;
    const int rowloc0 = w * 16 + g;
    float e2max = __int_as_float(g_e2max_bits);
    float margd[2], rmax[2], thr[2];
#pragma unroll
    for (int rs = 0; rs < 2; rs++) {
        margd[rs] = 0.015625f * sqrtf(g_x2[n0 + rowloc0 + rs * 8] * e2max) + 1.0e-3f;
        rmax[rs] = -CUDART_INF_F;
        thr[rs]  = -CUDART_INF_F;
    }
    const uint32_t boff = (uint32_t)(lr + ((lm >> 1) & 1) * 8) * PADB + ((lm & 1) << 4);

    for (int t = 0; t < NTILES; t++) {
        if (t < NTILES - 1) {   // prefetch next emb tile into other buffer
            const char* ge = (const char*)(g_eb + (size_t)(t + 1) * 128 * DIM);
            uint32_t db = sb + ZSZ + ((t + 1) & 1) * ZSZ;
#pragma unroll
            for (int u = 0; u < 16; u++) {
                int i = tid + u * 256;
                int row = i >> 5, q = i & 31;
                CPA16(db + row * PADB + q * 16, ge + row * 512 + q * 16);
            }
            CPA_COMMIT();
            CPA_WAIT1();
        } else {
            CPA_WAIT0();
        }
        __syncthreads();

        const uint32_t bB = sb + ZSZ + (t & 1) * ZSZ + boff;
#pragma unroll 1
        for (int nq = 0; nq < 4; nq++) {          // 32 codes per n-quad
            float C[4][4];
#pragma unroll
            for (int i = 0; i < 4; i++)
#pragma unroll
                for (int j = 0; j < 4; j++) C[i][j] = 0.f;

            uint32_t addr0 = bB + (uint32_t)(nq * 32) * PADB;
            uint32_t addr1 = addr0 + 16 * PADB;
#pragma unroll
            for (int ks = 0; ks < 16; ks++) {
                uint32_t b0[4], b1[4];
                LDSM4(b0, addr0 + ks * 32);
                LDSM4(b1, addr1 + ks * 32);
                mma16816(C[0], a[ks], b0[0], b0[1]);
                mma16816(C[1], a[ks], b0[2], b0[3]);
                mma16816(C[2], a[ks], b1[0], b1[1]);
                mma16816(C[3], a[ks], b1[2], b1[3]);
            }
            // epilogue: capture k iff dot >= rowmax - margd (superset of true argmin)
            int kc = t * 128 + nq * 32 + 2 * tq;
#pragma unroll
            for (int nt = 0; nt < 4; nt++) {
#pragma unroll
                for (int r = 0; r < 4; r++) {
                    float d = C[nt][r];
                    int rs = r >> 1;
                    if (d >= thr[rs]) {
                        int rl = rowloc0 + rs * 8;
                        int idx = atomicAdd(&scnt[rl], 1);
                        if (idx < CAP)
                            g_cand[(size_t)(n0 + rl) * CAP + idx] = kc + nt * 8 + (r & 1);
                        if (d > rmax[rs]) { rmax[rs] = d; thr[rs] = d - margd[rs]; }
                    }
                }
            }
        }
        // share running max across the 4 lanes owning each row (lanes 4g..4g+3)
#pragma unroll
        for (int rs = 0; rs < 2; rs++) {
            float m = rmax[rs];
            m = fmaxf(m, __shfl_xor_sync(0xffffffffu, m, 1));
            m = fmaxf(m, __shfl_xor_sync(0xffffffffu, m, 2));
            rmax[rs] = m;
            thr[rs] = m - margd[rs];
        }
        __syncthreads();
    }

    __syncthreads();
    if (tid < 128) {
        int c = scnt[tid];
        g_cnt[n0 + tid] = c < CAP ? c : CAP;
        g_over[n0 + tid] = (c > CAP) ? 1 : 0;
    }
}

// ---------------- phase 2: exact fp32 rescoring (round-2 bit-exact chain) ---
__global__ void vq_exact(const float* __restrict__ z_e, const float* __restrict__ emb) {
    __shared__ float zrow[8][DIM];
    int wid = threadIdx.x >> 5, lane = threadIdx.x & 31;
    int row = blockIdx.x * 8 + wid;
    {
        const float4* gz = (const float4*)(z_e + (size_t)row * DIM);
#pragma unroll
        for (int i = 0; i < 2; i++) {
            float4 v = gz[lane + 32 * i];
            *(float4*)&zrow[wid][4 * (lane + 32 * i)] = v;
        }
    }
    __syncwarp();
    const float* zr = zrow[wid];
    float x2 = 0.f;
    for (int d = 0; d < DIM; d++) x2 = __fmaf_rn(zr[d], zr[d], x2);

    float bt = CUDART_INF_F;
    int bk = 0x7fffffff;
    int cnt = g_cnt[row];
    bool over = g_over[row] != 0;
    int total = over ? KCODES : cnt;
    for (int c = lane; c < total; c += 32) {
        int k = over ? c : g_cand[(size_t)row * CAP + c];
        const float4* er = (const float4*)(emb + (size_t)k * DIM);
        float dot = 0.f;
#pragma unroll 8
        for (int q = 0; q < DIM / 4; q++) {
            float4 e4 = er[q];
            dot = __fmaf_rn(zr[4 * q + 0], e4.x, dot);
            dot = __fmaf_rn(zr[4 * q + 1], e4.y, dot);
            dot = __fmaf_rn(zr[4 * q + 2], e4.z, dot);
            dot = __fmaf_rn(zr[4 * q + 3], e4.w, dot);
        }
        float S = __fadd_rn(x2, g_e2[k]);
        float tt = __fadd_rn(S, -2.0f * dot);
        if (tt < bt || (tt == bt && k < bk)) { bt = tt; bk = k; }
    }
#pragma unroll
    for (int o = 16; o; o >>= 1) {
        float to = __shfl_down_sync(0xffffffffu, bt, o);
        int ko = __shfl_down_sync(0xffffffffu, bk, o);
        if (to < bt || (to == bt && ko < bk)) { bt = to; bk = ko; }
    }
    if (lane == 0) g_codes[row] = bk;
}

// ---------------- gather + losses ----------------
__global__ void vq_gather(const float* __restrict__ z_e, const float* __restrict__ emb,
                          float* __restrict__ out) {
    int row = blockIdx.x;
    int d = threadIdx.x;
    int code = g_codes[row];
    float ze = z_e[(size_t)row * DIM + d];
    float zq = emb[(size_t)code * DIM + d];
    float dif = __fsub_rn(zq, ze);
    out[(size_t)row * DIM + d] = __fadd_rn(ze, dif);
    float sq = __fmul_rn(dif, dif);
    __shared__ float ws[8];
#pragma unroll
    for (int o = 16; o; o >>= 1) sq += __shfl_down_sync(0xffffffffu, sq, o);
    if ((d & 31) == 0) ws[d >> 5] = sq;
    __syncthreads();
    if (d == 0) {
        float s = 0.f;
#pragma unroll
        for (int wq = 0; wq < 8; wq++) s += ws[wq];
        g_part[row] = (double)s;
        out[(size_t)NROWS * DIM + 1 + row] = (float)code;
    }
}

__global__ void vq_loss(float* __restrict__ out) {
    __shared__ double sd[1024];
    int tid = threadIdx.x;
    double s = 0.0;
    for (int i = tid; i < NROWS; i += 1024) s += g_part[i];
    sd[tid] = s;
    __syncthreads();
    for (int st = 512; st; st >>= 1) {
        if (tid < st) sd[tid] += sd[tid + st];
        __syncthreads();
    }
    if (tid == 0) {
        float m = (float)(sd[0] / (double)((size_t)NROWS * DIM));
        out[(size_t)NROWS * DIM] = __fadd_rn(m, 0.25f * m);
    }
}

// ---------------------------------------------------------------------------
extern "C" void kernel_launch(void* const* d_in, const int* in_sizes, int n_in,
                              void* d_out, int out_size) {
    const float* z_e = (const float*)d_in[0];
    const float* emb = (const float*)d_in[1];
    if (n_in >= 2 && in_sizes[0] == KCODES * DIM && in_sizes[1] == NROWS * DIM) {
        const float* t = z_e; z_e = emb; emb = t;
    }
    float* out = (float*)d_out;

    cudaFuncSetAttribute(vq_mma, cudaFuncAttributeMaxDynamicSharedMemorySize, SMEM_TOT);

    int conv_blocks = (NROWS * DIM + KCODES * DIM) / 4 / 256;
    conv_kernel<<<conv_blocks, 256>>>(z_e, emb);
    e2_kernel<<<KCODES / 8, 256>>>(emb);
    x2_kernel<<<NROWS / 8, 256>>>(z_e);
    vq_mma<<<NROWS / 128, 256, SMEM_TOT>>>();
    vq_exact<<<NROWS / 8, 256>>>(z_e, emb);
    vq_gather<<<NROWS, 256>>>(z_e, emb, out);
    vq_loss<<<1, 1024>>>(out);
}

// round 7
// speedup vs baseline: 72.8094x; 72.8094x over previous
#include <cuda_runtime.h>
#include <cuda_bf16.h>
#include <math_constants.h>
#include <cstdint>

#define NROWS 16384
#define KCODES 8192
#define DIM 256
#define CAP 64
#define NTILES 64          // 8192 / 128 codes per tile
#define PADB 528           // smem row pitch bytes (256 bf16 = 512 + 16 pad)
#define ZSZ (128 * PADB)   // 67584 per tile buffer
#define SMEM_TOT (3 * ZSZ + 512)

// ---------------- static device scratch ----------------
__device__ __align__(16) __nv_bfloat16 g_zb[NROWS * DIM];
__device__ __align__(16) __nv_bfloat16 g_eb[KCODES * DIM];
__device__ int    g_cand[NROWS * CAP];
__device__ int    g_cnt[NROWS];
__device__ unsigned char g_over[NROWS];
__device__ float  g_x2[NROWS];
__device__ float  g_e2[KCODES];
__device__ int    g_e2max_bits;
__device__ int    g_codes[NROWS];
__device__ double g_part[NROWS];

// ---------------- base-target PTX helpers ----------------
__device__ __forceinline__ uint32_t smem_u32(const void* p) {
    uint32_t a;
    asm("{ .reg .u64 t; cvta.to.shared.u64 t, %1; cvt.u32.u64 %0, t; }" : "=r"(a) : "l"(p));
    return a;
}
#define CPA16(dst, src) \
    asm volatile("cp.async.cg.shared.global [%0], [%1], 16;" :: "r"(dst), "l"(src))
#define CPA_COMMIT() asm volatile("cp.async.commit_group;" ::: "memory")
#define CPA_WAIT1()  asm volatile("cp.async.wait_group 1;" ::: "memory")
#define CPA_WAIT0()  asm volatile("cp.async.wait_group 0;" ::: "memory")
#define LDSM4(r, addr) \
    asm volatile("ldmatrix.sync.aligned.m8n8.x4.shared.b16 {%0,%1,%2,%3}, [%4];" \
                 : "=r"((r)[0]), "=r"((r)[1]), "=r"((r)[2]), "=r"((r)[3]) : "r"(addr))

__device__ __forceinline__ void mma16816(float* c, const uint32_t* a, uint32_t b0, uint32_t b1) {
    asm volatile(
        "mma.sync.aligned.m16n8k16.row.col.f32.bf16.bf16.f32 "
        "{%0,%1,%2,%3},{%4,%5,%6,%7},{%8,%9},{%0,%1,%2,%3};"
        : "+f"(c[0]), "+f"(c[1]), "+f"(c[2]), "+f"(c[3])
        : "r"(a[0]), "r"(a[1]), "r"(a[2]), "r"(a[3]), "r"(b0), "r"(b1));
}

// ---------------- aux kernels ----------------
__global__ void conv_kernel(const float* __restrict__ z, const float* __restrict__ e) {
    if (blockIdx.x == 0 && threadIdx.x == 0) g_e2max_bits = 0;
    size_t v4 = (size_t)blockIdx.x * 256 + threadIdx.x;
    const size_t NZ4 = (size_t)NROWS * DIM / 4;
    if (v4 < NZ4) {
        float4 f = ((const float4*)z)[v4];
        __nv_bfloat162* d = (__nv_bfloat162*)g_zb + v4 * 2;
        d[0] = __floats2bfloat162_rn(f.x, f.y);
        d[1] = __floats2bfloat162_rn(f.z, f.w);
    } else {
        size_t u = v4 - NZ4;
        float4 f = ((const float4*)e)[u];
        __nv_bfloat162* d = (__nv_bfloat162*)g_eb + u * 2;
        d[0] = __floats2bfloat162_rn(f.x, f.y);
        d[1] = __floats2bfloat162_rn(f.z, f.w);
    }
}

__global__ void e2_kernel(const float* __restrict__ emb) {
    int k = blockIdx.x * 8 + (threadIdx.x >> 5);
    int lane = threadIdx.x & 31;
    const float* p = emb + (size_t)k * DIM;
    float s = 0.f;
#pragma unroll
    for (int i = 0; i < 8; i++) { float v = p[lane + 32 * i]; s = __fmaf_rn(v, v, s); }
#pragma unroll
    for (int o = 16; o; o >>= 1) s += __shfl_down_sync(0xffffffffu, s, o);
    if (lane == 0) { g_e2[k] = s; atomicMax(&g_e2max_bits, __float_as_int(s)); }
}

__global__ void x2_kernel(const float* __restrict__ z) {
    int row = blockIdx.x * 8 + (threadIdx.x >> 5);
    int lane = threadIdx.x & 31;
    const float* p = z + (size_t)row * DIM;
    float s = 0.f;
#pragma unroll
    for (int i = 0; i < 8; i++) { float v = p[lane + 32 * i]; s = __fmaf_rn(v, v, s); }
#pragma unroll
    for (int o = 16; o; o >>= 1) s += __shfl_down_sync(0xffffffffu, s, o);
    if (lane == 0) g_x2[row] = s;
}

// ---------------- phase 1: mma.sync bf16 GEMM + dot-margin pruning ----------
__global__ __launch_bounds__(256, 1) void vq_mma() {
    extern __shared__ char sm[];
    int* scnt = (int*)(sm + 3 * ZSZ);
    const uint32_t sb = smem_u32(sm);
    const int tid = threadIdx.x, lane = tid & 31, w = tid >> 5;
    const int n0 = blockIdx.x * 128;

    if (tid < 128) scnt[tid] = 0;

    // prologue loads: z tile + emb tile 0 (one cp.async group)
    {
        const char* gz = (const char*)(g_zb + (size_t)n0 * DIM);
        const char* ge = (const char*)g_eb;
#pragma unroll
        for (int t = 0; t < 16; t++) {
            int i = tid + t * 256;
            int row = i >> 5, q = i & 31;
            CPA16(sb + row * PADB + q * 16, gz + row * 512 + q * 16);
        }
#pragma unroll
        for (int t = 0; t < 16; t++) {
            int i = tid + t * 256;
            int row = i >> 5, q = i & 31;
            CPA16(sb + ZSZ + row * PADB + q * 16, ge + row * 512 + q * 16);
        }
        CPA_COMMIT();
    }
    CPA_WAIT0();
    __syncthreads();

    // persistent A fragments: this warp's 16 rows x full D=256
    const int lm = lane >> 3, lr = lane & 7;
    uint32_t a[16][4];
    {
        uint32_t aAddr = sb + (uint32_t)(w * 16 + lr + (lm & 1) * 8) * PADB + ((lm >> 1) << 4);
#pragma unroll
        for (int ks = 0; ks < 16; ks++) LDSM4(a[ks], aAddr + ks * 32);
    }

    // pruning state: rows (w*16 + g) and (+8), g = lane>>2
    const int g = lane >> 2, tq = lane & 3;
    const int rowloc0 = w * 16 + g;
    float e2max = __int_as_float(g_e2max_bits);
    float margd[2], rmax[2], thr[2];
#pragma unroll
    for (int rs = 0; rs < 2; rs++) {
        // rigorous bf16 dot-error bound: 2^-7 * ||z|| * ||e||_max  (+ tie/rounding slack)
        margd[rs] = 0.0078125f * sqrtf(g_x2[n0 + rowloc0 + rs * 8] * e2max) + 1.0e-4f;
        rmax[rs] = -CUDART_INF_F;
        thr[rs]  = -CUDART_INF_F;
    }
    const uint32_t boff = (uint32_t)(lr + ((lm >> 1) & 1) * 8) * PADB + ((lm & 1) << 4);

    for (int t = 0; t < NTILES; t++) {
        if (t < NTILES - 1) {   // prefetch next emb tile into other buffer
            const char* ge = (const char*)(g_eb + (size_t)(t + 1) * 128 * DIM);
            uint32_t db = sb + ZSZ + ((t + 1) & 1) * ZSZ;
#pragma unroll
            for (int u = 0; u < 16; u++) {
                int i = tid + u * 256;
                int row = i >> 5, q = i & 31;
                CPA16(db + row * PADB + q * 16, ge + row * 512 + q * 16);
            }
            CPA_COMMIT();
            CPA_WAIT1();
        } else {
            CPA_WAIT0();
        }
        __syncthreads();

        const uint32_t bB = sb + ZSZ + (t & 1) * ZSZ + boff;
#pragma unroll 1
        for (int nq = 0; nq < 4; nq++) {          // 32 codes per n-quad
            float C[4][4];
#pragma unroll
            for (int i = 0; i < 4; i++)
#pragma unroll
                for (int j = 0; j < 4; j++) C[i][j] = 0.f;

            uint32_t addr0 = bB + (uint32_t)(nq * 32) * PADB;
            uint32_t addr1 = addr0 + 16 * PADB;
#pragma unroll
            for (int ks = 0; ks < 16; ks++) {
                uint32_t b0[4], b1[4];
                LDSM4(b0, addr0 + ks * 32);
                LDSM4(b1, addr1 + ks * 32);
                mma16816(C[0], a[ks], b0[0], b0[1]);
                mma16816(C[1], a[ks], b0[2], b0[3]);
                mma16816(C[2], a[ks], b1[0], b1[1]);
                mma16816(C[3], a[ks], b1[2], b1[3]);
            }
            // epilogue: capture k iff dot >= rowmax - margd (superset of true argmin)
            int kc = t * 128 + nq * 32 + 2 * tq;
#pragma unroll
            for (int nt = 0; nt < 4; nt++) {
#pragma unroll
                for (int r = 0; r < 4; r++) {
                    float d = C[nt][r];
                    int rs = r >> 1;
                    if (d >= thr[rs]) {
                        int rl = rowloc0 + rs * 8;
                        int idx = atomicAdd(&scnt[rl], 1);
                        if (idx < CAP)
                            g_cand[(size_t)(n0 + rl) * CAP + idx] = kc + nt * 8 + (r & 1);
                        if (d > rmax[rs]) { rmax[rs] = d; thr[rs] = d - margd[rs]; }
                    }
                }
            }
            // share running max across the 4 owner lanes after every 32 codes:
            // keeps prefix-capture count low (threshold tightens quickly)
#pragma unroll
            for (int rs = 0; rs < 2; rs++) {
                float m = rmax[rs];
                m = fmaxf(m, __shfl_xor_sync(0xffffffffu, m, 1));
                m = fmaxf(m, __shfl_xor_sync(0xffffffffu, m, 2));
                rmax[rs] = m;
                thr[rs] = m - margd[rs];
            }
        }
        __syncthreads();
    }

    __syncthreads();
    if (tid < 128) {
        int c = scnt[tid];
        g_cnt[n0 + tid] = c < CAP ? c : CAP;
        g_over[n0 + tid] = (c > CAP) ? 1 : 0;
    }
}

// ---------------- phase 2: exact fp32 rescoring (round-2 bit-exact chain) ---
__global__ void vq_exact(const float* __restrict__ z_e, const float* __restrict__ emb) {
    __shared__ float zrow[8][DIM];
    int wid = threadIdx.x >> 5, lane = threadIdx.x & 31;
    int row = blockIdx.x * 8 + wid;
    {
        const float4* gz = (const float4*)(z_e + (size_t)row * DIM);
#pragma unroll
        for (int i = 0; i < 2; i++) {
            float4 v = gz[lane + 32 * i];
            *(float4*)&zrow[wid][4 * (lane + 32 * i)] = v;
        }
    }
    __syncwarp();
    const float* zr = zrow[wid];
    float x2 = 0.f;
    for (int d = 0; d < DIM; d++) x2 = __fmaf_rn(zr[d], zr[d], x2);

    float bt = CUDART_INF_F;
    int bk = 0x7fffffff;
    int cnt = g_cnt[row];
    bool over = g_over[row] != 0;
    int total = over ? KCODES : cnt;
    for (int c = lane; c < total; c += 32) {
        int k = over ? c : g_cand[(size_t)row * CAP + c];
        const float4* er = (const float4*)(emb + (size_t)k * DIM);
        float dot = 0.f;
#pragma unroll 8
        for (int q = 0; q < DIM / 4; q++) {
            float4 e4 = er[q];
            dot = __fmaf_rn(zr[4 * q + 0], e4.x, dot);
            dot = __fmaf_rn(zr[4 * q + 1], e4.y, dot);
            dot = __fmaf_rn(zr[4 * q + 2], e4.z, dot);
            dot = __fmaf_rn(zr[4 * q + 3], e4.w, dot);
        }
        float S = __fadd_rn(x2, g_e2[k]);
        float tt = __fadd_rn(S, -2.0f * dot);
        if (tt < bt || (tt == bt && k < bk)) { bt = tt; bk = k; }
    }
#pragma unroll
    for (int o = 16; o; o >>= 1) {
        float to = __shfl_down_sync(0xffffffffu, bt, o);
        int ko = __shfl_down_sync(0xffffffffu, bk, o);
        if (to < bt || (to == bt && ko < bk)) { bt = to; bk = ko; }
    }
    if (lane == 0) g_codes[row] = bk;
}

// ---------------- gather + losses ----------------
__global__ void vq_gather(const float* __restrict__ z_e, const float* __restrict__ emb,
                          float* __restrict__ out) {
    int row = blockIdx.x;
    int d = threadIdx.x;
    int code = g_codes[row];
    float ze = z_e[(size_t)row * DIM + d];
    float zq = emb[(size_t)code * DIM + d];
    float dif = __fsub_rn(zq, ze);
    out[(size_t)row * DIM + d] = __fadd_rn(ze, dif);
    float sq = __fmul_rn(dif, dif);
    __shared__ float ws[8];
#pragma unroll
    for (int o = 16; o; o >>= 1) sq += __shfl_down_sync(0xffffffffu, sq, o);
    if ((d & 31) == 0) ws[d >> 5] = sq;
    __syncthreads();
    if (d == 0) {
        float s = 0.f;
#pragma unroll
        for (int wq = 0; wq < 8; wq++) s += ws[wq];
        g_part[row] = (double)s;
        out[(size_t)NROWS * DIM + 1 + row] = (float)code;
    }
}

__global__ void vq_loss(float* __restrict__ out) {
    __shared__ double sd[1024];
    int tid = threadIdx.x;
    double s = 0.0;
    for (int i = tid; i < NROWS; i += 1024) s += g_part[i];
    sd[tid] = s;
    __syncthreads();
    for (int st = 512; st; st >>= 1) {
        if (tid < st) sd[tid] += sd[tid + st];
        __syncthreads();
    }
    if (tid == 0) {
        float m = (float)(sd[0] / (double)((size_t)NROWS * DIM));
        out[(size_t)NROWS * DIM] = __fadd_rn(m, 0.25f * m);
    }
}

// ---------------------------------------------------------------------------
extern "C" void kernel_launch(void* const* d_in, const int* in_sizes, int n_in,
                              void* d_out, int out_size) {
    const float* z_e = (const float*)d_in[0];
    const float* emb = (const float*)d_in[1];
    if (n_in >= 2 && in_sizes[0] == KCODES * DIM && in_sizes[1] == NROWS * DIM) {
        const float* t = z_e; z_e = emb; emb = t;
    }
    float* out = (float*)d_out;

    cudaFuncSetAttribute(vq_mma, cudaFuncAttributeMaxDynamicSharedMemorySize, SMEM_TOT);

    int conv_blocks = (NROWS * DIM + KCODES * DIM) / 4 / 256;
    conv_kernel<<<conv_blocks, 256>>>(z_e, emb);
    e2_kernel<<<KCODES / 8, 256>>>(emb);
    x2_kernel<<<NROWS / 8, 256>>>(z_e);
    vq_mma<<<NROWS / 128, 256, SMEM_TOT>>>();
    vq_exact<<<NROWS / 8, 256>>>(z_e, emb);
    vq_gather<<<NROWS, 256>>>(z_e, emb, out);
    vq_loss<<<1, 1024>>>(out);
}